// round 14
// baseline (speedup 1.0000x reference)
#include <cuda_runtime.h>
#include <cuda_bf16.h>

// BalancedBCE round 11 = R9 stream (no_allocate + concentrated L2 prefetch,
// single balanced wave) + two-level reduction tickets:
//   level 1: last block per sample reduces its 19 partials -> 4 values
//   level 2: last sample-leader reduces 64x4 values -> scalar
// Shrinks the serial post-stream tail from ~3.6K reads to 256.

#define BATCH   64
#define BPB     19      // 64*19 = 1216 = 8 CTAs x 152 SMs, single balanced wave
#define THREADS 256
#define NBLOCKS (BATCH * BPB)

__device__ float g_part[NBLOCKS * 3];          // [blk][qty][b] as before
__device__ float g_samp[BATCH * 4];            // per-sample {wpos,wneg,cpos,cneg}
__device__ unsigned int g_ticket_s[BATCH];     // per-sample tickets
__device__ unsigned int g_ticket_g;            // global ticket over sample leaders

__device__ __forceinline__ float4 ldg_na(const float4* p) {
    float4 v;
    asm volatile("ld.global.nc.L1::no_allocate.v4.f32 {%0,%1,%2,%3}, [%4];"
                 : "=f"(v.x), "=f"(v.y), "=f"(v.z), "=f"(v.w)
                 : "l"(p));
    return v;
}

__device__ __forceinline__ void pf_l2(const float4* p) {
    asm volatile("prefetch.global.L2 [%0];" :: "l"(p));
}

__device__ __forceinline__ void block_reduce3(float& a, float& b, float& c) {
    #pragma unroll
    for (int off = 16; off > 0; off >>= 1) {
        a += __shfl_down_sync(0xFFFFFFFFu, a, off);
        b += __shfl_down_sync(0xFFFFFFFFu, b, off);
        c += __shfl_down_sync(0xFFFFFFFFu, c, off);
    }
    __shared__ float sa[THREADS / 32], sb[THREADS / 32], sc[THREADS / 32];
    int lane = threadIdx.x & 31;
    int warp = threadIdx.x >> 5;
    if (lane == 0) { sa[warp] = a; sb[warp] = b; sc[warp] = c; }
    __syncthreads();
    if (warp == 0) {
        a = (lane < THREADS / 32) ? sa[lane] : 0.0f;
        b = (lane < THREADS / 32) ? sb[lane] : 0.0f;
        c = (lane < THREADS / 32) ? sc[lane] : 0.0f;
        #pragma unroll
        for (int off = (THREADS / 64); off > 0; off >>= 1) {
            a += __shfl_down_sync(0xFFFFFFFFu, a, off);
            b += __shfl_down_sync(0xFFFFFFFFu, b, off);
            c += __shfl_down_sync(0xFFFFFFFFu, c, off);
        }
    }
}

struct Acc {
    float A, Bp, Cp, cnt, sp_log, sn_log;
};

__device__ __forceinline__ void body4(const float4& xv, const float4& tv, Acc& s) {
    float pp = 1.0f, pn = 1.0f;
    float xs[4] = {xv.x, xv.y, xv.z, xv.w};
    float ts[4] = {tv.x, tv.y, tv.z, tv.w};
    #pragma unroll
    for (int k = 0; k < 4; k++) {
        float x = xs[k];
        float t = ts[k];                 // exactly 0.0 or 1.0
        float e = __expf(-fabsf(x));
        float u = t * e;
        pp = fmaf(u, pp, pp);            // pp *= (1 + t*e)
        pn = fmaf(e - u, pn, pn);        // pn *= (1 + (1-t)*e)
        float w  = fmaxf(x, 0.0f);
        float wn = fmaxf(-x, 0.0f);
        s.A   += w;
        s.Bp   = fmaf(t, wn, s.Bp);
        s.Cp   = fmaf(t, w, s.Cp);
        s.cnt += t;
    }
    s.sp_log += __logf(pp);
    s.sn_log += __logf(pn);
}

__global__ void __launch_bounds__(THREADS, 8)
bce_fused_kernel(const float* __restrict__ x_all,
                 const float* __restrict__ t_all,
                 int n_per_sample,
                 float* __restrict__ out)
{
    const int b   = blockIdx.y;
    const int blk = blockIdx.x;

    const float4* __restrict__ x4 =
        reinterpret_cast<const float4*>(x_all + (size_t)b * n_per_sample);
    const float4* __restrict__ t4 =
        reinterpret_cast<const float4*>(t_all + (size_t)b * n_per_sample);
    const int n4 = n_per_sample >> 2;     // 65536 for the real shape
    const int STRIDE = BPB * THREADS;     // 4864

    Acc s = {0.0f, 0.0f, 0.0f, 0.0f, 0.0f, 0.0f};

    const bool pf_lane = ((threadIdx.x & 7) == 0);   // 1 pf per 128B line (R9 scheme)

    int i = blk * THREADS + threadIdx.x;
    if (pf_lane) {          // warm-up: cover double-steps 1 and 2
        int p0 = min(i + 2 * STRIDE, n4 - 1);
        int p1 = min(i + 3 * STRIDE, n4 - 1);
        pf_l2(x4 + p0); pf_l2(t4 + p0);
        pf_l2(x4 + p1); pf_l2(t4 + p1);
    }

    for (; i + STRIDE < n4; i += 2 * STRIDE) {
        if (pf_lane) {      // prefetch one double-step ahead (distance 2)
            int p0 = min(i + 4 * STRIDE, n4 - 1);
            int p1 = min(i + 5 * STRIDE, n4 - 1);
            pf_l2(x4 + p0); pf_l2(t4 + p0);
            pf_l2(x4 + p1); pf_l2(t4 + p1);
        }
        float4 xa = ldg_na(x4 + i);
        float4 xb = ldg_na(x4 + i + STRIDE);
        float4 ta = ldg_na(t4 + i);
        float4 tb = ldg_na(t4 + i + STRIDE);
        body4(xa, ta, s);
        body4(xb, tb, s);
    }
    if (i < n4) {
        float4 xa = ldg_na(x4 + i);
        float4 ta = ldg_na(t4 + i);
        body4(xa, ta, s);
    }

    float sp = s.Bp + s.sp_log;
    float sn = (s.A - s.Cp) + s.sn_log;
    float cnt = s.cnt;

    block_reduce3(sp, sn, cnt);

    // ---- level 1: per-sample ticket ----
    __shared__ bool am_sample_last;
    if (threadIdx.x == 0) {
        g_part[blk * 192 +   0 + b] = sp;
        g_part[blk * 192 +  64 + b] = sn;
        g_part[blk * 192 + 128 + b] = cnt;
        __threadfence();
        unsigned int t = atomicAdd(&g_ticket_s[b], 1u);
        am_sample_last = (t == (unsigned)(BPB - 1));
    }
    __syncthreads();
    if (!am_sample_last) return;

    // last block of sample b: reduce its 19 partials (warp 0 does it)
    __shared__ bool am_global_last;
    if (threadIdx.x < 32) {
        float Sp = 0.0f, Sn = 0.0f, C = 0.0f;
        // 19 partials read by lanes 0..18, then warp-reduce
        if (threadIdx.x < BPB) {
            Sp = g_part[threadIdx.x * 192 +   0 + b];
            Sn = g_part[threadIdx.x * 192 +  64 + b];
            C  = g_part[threadIdx.x * 192 + 128 + b];
        }
        #pragma unroll
        for (int off = 16; off > 0; off >>= 1) {
            Sp += __shfl_down_sync(0xFFFFFFFFu, Sp, off);
            Sn += __shfl_down_sync(0xFFFFFFFFu, Sn, off);
            C  += __shfl_down_sync(0xFFFFFFFFu, C,  off);
        }
        if (threadIdx.x == 0) {
            float N     = (float)n_per_sample;
            float tmean = C / N;
            g_samp[b * 4 + 0] = (1.0f - tmean) * Sp;   // wpos
            g_samp[b * 4 + 1] = tmean * Sn;            // wneg
            g_samp[b * 4 + 2] = C;                     // cpos
            g_samp[b * 4 + 3] = N - C;                 // cneg
            g_ticket_s[b] = 0;                         // reset for next replay
            __threadfence();
            unsigned int t = atomicAdd(&g_ticket_g, 1u);
            am_global_last = (t == (unsigned)(BATCH - 1));
        }
    }
    __syncthreads();
    if (!am_global_last) return;

    // ---- level 2: final 64-sample reduction (warp 0, 2 samples per lane) ----
    if (threadIdx.x < 32) {
        int l = threadIdx.x;
        float wpos = g_samp[l * 4 + 0] + g_samp[(l + 32) * 4 + 0];
        float wneg = g_samp[l * 4 + 1] + g_samp[(l + 32) * 4 + 1];
        float cpos = g_samp[l * 4 + 2] + g_samp[(l + 32) * 4 + 2];
        float cneg = g_samp[l * 4 + 3] + g_samp[(l + 32) * 4 + 3];
        #pragma unroll
        for (int off = 16; off > 0; off >>= 1) {
            wpos += __shfl_down_sync(0xFFFFFFFFu, wpos, off);
            wneg += __shfl_down_sync(0xFFFFFFFFu, wneg, off);
            cpos += __shfl_down_sync(0xFFFFFFFFu, cpos, off);
            cneg += __shfl_down_sync(0xFFFFFFFFu, cneg, off);
        }
        if (threadIdx.x == 0) {
            out[0] = wpos / cpos + wneg / cneg;
            g_ticket_g = 0;   // reset for next graph replay (deterministic)
        }
    }
}

extern "C" void kernel_launch(void* const* d_in, const int* in_sizes, int n_in,
                              void* d_out, int out_size) {
    const float* x = (const float*)d_in[0];
    const float* t = (const float*)d_in[1];
    float* out = (float*)d_out;

    const int total = in_sizes[0];
    const int n_per_sample = total / BATCH;

    dim3 grid(BPB, BATCH);
    bce_fused_kernel<<<grid, THREADS>>>(x, t, n_per_sample, out);
}

// round 15
// speedup vs baseline: 1.0954x; 1.0954x over previous
#include <cuda_runtime.h>
#include <cuda_bf16.h>

// BalancedBCE round 12 = R9 skeleton (no_allocate loads, single balanced wave,
// single-ticket fused epilogue) with the L2 prefetch moved entirely up front:
// each CTA enqueues its whole remaining chunk as fire-and-forget L2 prefetches
// before the main loop, eliminating the demand-miss ramp. Loop body is
// prefetch-free.

#define BATCH   64
#define BPB     19      // 64*19 = 1216 = 8 CTAs x 152 SMs, single balanced wave
#define THREADS 256
#define NBLOCKS (BATCH * BPB)

__device__ float g_part[NBLOCKS * 3];
__device__ unsigned int g_ticket = 0;

__device__ __forceinline__ float4 ldg_na(const float4* p) {
    float4 v;
    asm volatile("ld.global.nc.L1::no_allocate.v4.f32 {%0,%1,%2,%3}, [%4];"
                 : "=f"(v.x), "=f"(v.y), "=f"(v.z), "=f"(v.w)
                 : "l"(p));
    return v;
}

__device__ __forceinline__ void pf_l2(const float4* p) {
    asm volatile("prefetch.global.L2 [%0];" :: "l"(p));
}

__device__ __forceinline__ void block_reduce3(float& a, float& b, float& c) {
    #pragma unroll
    for (int off = 16; off > 0; off >>= 1) {
        a += __shfl_down_sync(0xFFFFFFFFu, a, off);
        b += __shfl_down_sync(0xFFFFFFFFu, b, off);
        c += __shfl_down_sync(0xFFFFFFFFu, c, off);
    }
    __shared__ float sa[THREADS / 32], sb[THREADS / 32], sc[THREADS / 32];
    int lane = threadIdx.x & 31;
    int warp = threadIdx.x >> 5;
    if (lane == 0) { sa[warp] = a; sb[warp] = b; sc[warp] = c; }
    __syncthreads();
    if (warp == 0) {
        a = (lane < THREADS / 32) ? sa[lane] : 0.0f;
        b = (lane < THREADS / 32) ? sb[lane] : 0.0f;
        c = (lane < THREADS / 32) ? sc[lane] : 0.0f;
        #pragma unroll
        for (int off = (THREADS / 64); off > 0; off >>= 1) {
            a += __shfl_down_sync(0xFFFFFFFFu, a, off);
            b += __shfl_down_sync(0xFFFFFFFFu, b, off);
            c += __shfl_down_sync(0xFFFFFFFFu, c, off);
        }
    }
}

struct Acc {
    float A, Bp, Cp, cnt, sp_log, sn_log;
};

__device__ __forceinline__ void body4(const float4& xv, const float4& tv, Acc& s) {
    float pp = 1.0f, pn = 1.0f;
    float xs[4] = {xv.x, xv.y, xv.z, xv.w};
    float ts[4] = {tv.x, tv.y, tv.z, tv.w};
    #pragma unroll
    for (int k = 0; k < 4; k++) {
        float x = xs[k];
        float t = ts[k];                 // exactly 0.0 or 1.0
        float e = __expf(-fabsf(x));
        float u = t * e;
        pp = fmaf(u, pp, pp);            // pp *= (1 + t*e)
        pn = fmaf(e - u, pn, pn);        // pn *= (1 + (1-t)*e)
        float w  = fmaxf(x, 0.0f);
        float wn = fmaxf(-x, 0.0f);
        s.A   += w;
        s.Bp   = fmaf(t, wn, s.Bp);
        s.Cp   = fmaf(t, w, s.Cp);
        s.cnt += t;
    }
    s.sp_log += __logf(pp);
    s.sn_log += __logf(pn);
}

__global__ void __launch_bounds__(THREADS, 8)
bce_fused_kernel(const float* __restrict__ x_all,
                 const float* __restrict__ t_all,
                 int n_per_sample,
                 float* __restrict__ out)
{
    const int b   = blockIdx.y;
    const int blk = blockIdx.x;

    const float4* __restrict__ x4 =
        reinterpret_cast<const float4*>(x_all + (size_t)b * n_per_sample);
    const float4* __restrict__ t4 =
        reinterpret_cast<const float4*>(t_all + (size_t)b * n_per_sample);
    const int n4 = n_per_sample >> 2;     // 65536 for the real shape
    const int STRIDE = BPB * THREADS;     // 4864

    Acc s = {0.0f, 0.0f, 0.0f, 0.0f, 0.0f, 0.0f};

    const bool pf_lane = ((threadIdx.x & 7) == 0);   // 1 pf per 128B line
    const int i0 = blk * THREADS + threadIdx.x;

    // Up-front prefetch of the CTA's entire remaining chunk (fire-and-forget).
    // Steps 0 and 1 are demand-loaded immediately; everything else is queued
    // to L2 before the main loop starts, so DRAM runs at its own max rate
    // and demand loads ride L2 hits for the whole kernel.
    if (pf_lane) {
        for (int j = i0 + 2 * STRIDE; j < n4; j += STRIDE) {
            pf_l2(x4 + j);
            pf_l2(t4 + j);
        }
    }

    int i = i0;
    for (; i + STRIDE < n4; i += 2 * STRIDE) {
        float4 xa = ldg_na(x4 + i);
        float4 xb = ldg_na(x4 + i + STRIDE);
        float4 ta = ldg_na(t4 + i);
        float4 tb = ldg_na(t4 + i + STRIDE);
        body4(xa, ta, s);
        body4(xb, tb, s);
    }
    if (i < n4) {           // ragged tail (covered by up-front prefetch)
        float4 xa = ldg_na(x4 + i);
        float4 ta = ldg_na(t4 + i);
        body4(xa, ta, s);
    }

    float sp = s.Bp + s.sp_log;
    float sn = (s.A - s.Cp) + s.sn_log;
    float cnt = s.cnt;

    block_reduce3(sp, sn, cnt);

    __shared__ bool am_last;
    if (threadIdx.x == 0) {
        g_part[blk * 192 +   0 + b] = sp;
        g_part[blk * 192 +  64 + b] = sn;
        g_part[blk * 192 + 128 + b] = cnt;
        __threadfence();
        unsigned int t = atomicAdd(&g_ticket, 1u);
        am_last = (t == (unsigned)(NBLOCKS - 1));
    }
    __syncthreads();
    if (!am_last) return;

    // ---- last block: final reduction ----
    float wpos = 0.0f, wneg = 0.0f, cpos = 0.0f, cneg = 0.0f;
    if (threadIdx.x < BATCH) {
        const int bb = threadIdx.x;
        float Sp = 0.0f, Sn = 0.0f, C = 0.0f;
        #pragma unroll
        for (int j = 0; j < BPB; j++) {
            Sp += g_part[j * 192 +   0 + bb];
            Sn += g_part[j * 192 +  64 + bb];
            C  += g_part[j * 192 + 128 + bb];
        }
        float N     = (float)n_per_sample;
        float tmean = C / N;
        wpos = (1.0f - tmean) * Sp;
        wneg = tmean * Sn;
        cpos = C;
        cneg = N - C;
    }

    __shared__ float s0[2], s1[2], s2[2], s3[2];
    #pragma unroll
    for (int off = 16; off > 0; off >>= 1) {
        wpos += __shfl_down_sync(0xFFFFFFFFu, wpos, off);
        wneg += __shfl_down_sync(0xFFFFFFFFu, wneg, off);
        cpos += __shfl_down_sync(0xFFFFFFFFu, cpos, off);
        cneg += __shfl_down_sync(0xFFFFFFFFu, cneg, off);
    }
    int lane = threadIdx.x & 31;
    int warp = threadIdx.x >> 5;
    if (lane == 0 && warp < 2) { s0[warp] = wpos; s1[warp] = wneg; s2[warp] = cpos; s3[warp] = cneg; }
    __syncthreads();
    if (threadIdx.x == 0) {
        float WP = s0[0] + s0[1];
        float WN = s1[0] + s1[1];
        float CP = s2[0] + s2[1];
        float CN = s3[0] + s3[1];
        out[0] = WP / CP + WN / CN;
        g_ticket = 0;   // reset for next graph replay (deterministic)
    }
}

extern "C" void kernel_launch(void* const* d_in, const int* in_sizes, int n_in,
                              void* d_out, int out_size) {
    const float* x = (const float*)d_in[0];
    const float* t = (const float*)d_in[1];
    float* out = (float*)d_out;

    const int total = in_sizes[0];
    const int n_per_sample = total / BATCH;

    dim3 grid(BPB, BATCH);
    bce_fused_kernel<<<grid, THREADS>>>(x, t, n_per_sample, out);
}

// round 16
// speedup vs baseline: 1.1000x; 1.0042x over previous
#include <cuda_runtime.h>
#include <cuda_bf16.h>

// BalancedBCE round 13: per-CTA CONTIGUOUS chunks for DRAM row-buffer locality.
//  - BPB=16 -> each CTA owns a contiguous 16384-element (64KB) chunk
//  - exactly 8 clean double-steps per CTA (no ragged tail, fixed trip count)
//  - up-front fire-and-forget L2 prefetch of the whole chunk
//  - ld.global.nc.L1::no_allocate demand loads
//  - grouped-log math, single-ticket fused epilogue

#define BATCH   64
#define BPB     16      // 64*16 = 1024 CTAs, contiguous 4096-float4 chunks
#define THREADS 256
#define NBLOCKS (BATCH * BPB)
#define CHUNK4  4096    // float4s per CTA chunk (65536 / 16)

__device__ float g_part[NBLOCKS * 3];
__device__ unsigned int g_ticket = 0;

__device__ __forceinline__ float4 ldg_na(const float4* p) {
    float4 v;
    asm volatile("ld.global.nc.L1::no_allocate.v4.f32 {%0,%1,%2,%3}, [%4];"
                 : "=f"(v.x), "=f"(v.y), "=f"(v.z), "=f"(v.w)
                 : "l"(p));
    return v;
}

__device__ __forceinline__ void pf_l2(const float4* p) {
    asm volatile("prefetch.global.L2 [%0];" :: "l"(p));
}

__device__ __forceinline__ void block_reduce3(float& a, float& b, float& c) {
    #pragma unroll
    for (int off = 16; off > 0; off >>= 1) {
        a += __shfl_down_sync(0xFFFFFFFFu, a, off);
        b += __shfl_down_sync(0xFFFFFFFFu, b, off);
        c += __shfl_down_sync(0xFFFFFFFFu, c, off);
    }
    __shared__ float sa[THREADS / 32], sb[THREADS / 32], sc[THREADS / 32];
    int lane = threadIdx.x & 31;
    int warp = threadIdx.x >> 5;
    if (lane == 0) { sa[warp] = a; sb[warp] = b; sc[warp] = c; }
    __syncthreads();
    if (warp == 0) {
        a = (lane < THREADS / 32) ? sa[lane] : 0.0f;
        b = (lane < THREADS / 32) ? sb[lane] : 0.0f;
        c = (lane < THREADS / 32) ? sc[lane] : 0.0f;
        #pragma unroll
        for (int off = (THREADS / 64); off > 0; off >>= 1) {
            a += __shfl_down_sync(0xFFFFFFFFu, a, off);
            b += __shfl_down_sync(0xFFFFFFFFu, b, off);
            c += __shfl_down_sync(0xFFFFFFFFu, c, off);
        }
    }
}

struct Acc {
    float A, Bp, Cp, cnt, sp_log, sn_log;
};

__device__ __forceinline__ void body4(const float4& xv, const float4& tv, Acc& s) {
    float pp = 1.0f, pn = 1.0f;
    float xs[4] = {xv.x, xv.y, xv.z, xv.w};
    float ts[4] = {tv.x, tv.y, tv.z, tv.w};
    #pragma unroll
    for (int k = 0; k < 4; k++) {
        float x = xs[k];
        float t = ts[k];                 // exactly 0.0 or 1.0
        float e = __expf(-fabsf(x));
        float u = t * e;
        pp = fmaf(u, pp, pp);            // pp *= (1 + t*e)
        pn = fmaf(e - u, pn, pn);        // pn *= (1 + (1-t)*e)
        float w  = fmaxf(x, 0.0f);
        float wn = fmaxf(-x, 0.0f);
        s.A   += w;
        s.Bp   = fmaf(t, wn, s.Bp);
        s.Cp   = fmaf(t, w, s.Cp);
        s.cnt += t;
    }
    s.sp_log += __logf(pp);
    s.sn_log += __logf(pn);
}

__global__ void __launch_bounds__(THREADS, 8)
bce_fused_kernel(const float* __restrict__ x_all,
                 const float* __restrict__ t_all,
                 int n_per_sample,
                 float* __restrict__ out)
{
    const int b   = blockIdx.y;
    const int blk = blockIdx.x;

    const int chunk4 = (n_per_sample >> 2) / BPB;   // 4096 for real shape
    const float4* __restrict__ x4 =
        reinterpret_cast<const float4*>(x_all + (size_t)b * n_per_sample) +
        (size_t)blk * chunk4;
    const float4* __restrict__ t4 =
        reinterpret_cast<const float4*>(t_all + (size_t)b * n_per_sample) +
        (size_t)blk * chunk4;

    Acc s = {0.0f, 0.0f, 0.0f, 0.0f, 0.0f, 0.0f};

    const bool pf_lane = ((threadIdx.x & 7) == 0);   // 1 pf per 128B line

    // up-front prefetch of the whole chunk beyond the first double-step
    if (pf_lane) {
        for (int j = 2 * THREADS + (int)threadIdx.x; j < chunk4; j += THREADS) {
            pf_l2(x4 + j);
            pf_l2(t4 + j);
        }
    }

    int i = threadIdx.x;
    // contiguous walk: fixed trip count (8 double-steps for the real shape)
    for (; i + THREADS < chunk4; i += 2 * THREADS) {
        float4 xa = ldg_na(x4 + i);
        float4 xb = ldg_na(x4 + i + THREADS);
        float4 ta = ldg_na(t4 + i);
        float4 tb = ldg_na(t4 + i + THREADS);
        body4(xa, ta, s);
        body4(xb, tb, s);
    }
    if (i < chunk4) {       // safety tail for non-multiple shapes
        float4 xa = ldg_na(x4 + i);
        float4 ta = ldg_na(t4 + i);
        body4(xa, ta, s);
    }

    float sp = s.Bp + s.sp_log;
    float sn = (s.A - s.Cp) + s.sn_log;
    float cnt = s.cnt;

    block_reduce3(sp, sn, cnt);

    __shared__ bool am_last;
    if (threadIdx.x == 0) {
        g_part[blk * 192 +   0 + b] = sp;
        g_part[blk * 192 +  64 + b] = sn;
        g_part[blk * 192 + 128 + b] = cnt;
        __threadfence();
        unsigned int t = atomicAdd(&g_ticket, 1u);
        am_last = (t == (unsigned)(NBLOCKS - 1));
    }
    __syncthreads();
    if (!am_last) return;

    // ---- last block: final reduction ----
    float wpos = 0.0f, wneg = 0.0f, cpos = 0.0f, cneg = 0.0f;
    if (threadIdx.x < BATCH) {
        const int bb = threadIdx.x;
        float Sp = 0.0f, Sn = 0.0f, C = 0.0f;
        #pragma unroll
        for (int j = 0; j < BPB; j++) {
            Sp += g_part[j * 192 +   0 + bb];
            Sn += g_part[j * 192 +  64 + bb];
            C  += g_part[j * 192 + 128 + bb];
        }
        float N     = (float)n_per_sample;
        float tmean = C / N;
        wpos = (1.0f - tmean) * Sp;
        wneg = tmean * Sn;
        cpos = C;
        cneg = N - C;
    }

    __shared__ float s0[2], s1[2], s2[2], s3[2];
    #pragma unroll
    for (int off = 16; off > 0; off >>= 1) {
        wpos += __shfl_down_sync(0xFFFFFFFFu, wpos, off);
        wneg += __shfl_down_sync(0xFFFFFFFFu, wneg, off);
        cpos += __shfl_down_sync(0xFFFFFFFFu, cpos, off);
        cneg += __shfl_down_sync(0xFFFFFFFFu, cneg, off);
    }
    int lane = threadIdx.x & 31;
    int warp = threadIdx.x >> 5;
    if (lane == 0 && warp < 2) { s0[warp] = wpos; s1[warp] = wneg; s2[warp] = cpos; s3[warp] = cneg; }
    __syncthreads();
    if (threadIdx.x == 0) {
        float WP = s0[0] + s0[1];
        float WN = s1[0] + s1[1];
        float CP = s2[0] + s2[1];
        float CN = s3[0] + s3[1];
        out[0] = WP / CP + WN / CN;
        g_ticket = 0;   // reset for next graph replay (deterministic)
    }
}

extern "C" void kernel_launch(void* const* d_in, const int* in_sizes, int n_in,
                              void* d_out, int out_size) {
    const float* x = (const float*)d_in[0];
    const float* t = (const float*)d_in[1];
    float* out = (float*)d_out;

    const int total = in_sizes[0];
    const int n_per_sample = total / BATCH;

    dim3 grid(BPB, BATCH);
    bce_fused_kernel<<<grid, THREADS>>>(x, t, n_per_sample, out);
}